// round 15
// baseline (speedup 1.0000x reference)
#include <cuda_runtime.h>
#include <math.h>
#include <string.h>
#include <stdint.h>

// ---------------------------------------------------------------------------
// Problem constants
// ---------------------------------------------------------------------------
#define NM_MAX 50000
#define ND_MAX 20000
#define EMAX   700000
#define FEAT   128
#define SCAN_CHUNK 2048   // elements per CSR-scan block (256 thr x 8)

// Scratch (device globals: allocation-free rule)
__device__ float g_movie[(size_t)NM_MAX * FEAT];
__device__ float g_user1[(size_t)ND_MAX * FEAT];
__device__ float g_user2[(size_t)ND_MAX * FEAT];

// CSR-build scratch
__device__ int   g_cnt_m[NM_MAX + 1];
__device__ int   g_off_m[NM_MAX + 1];
__device__ int   g_cur_m[NM_MAX];
__device__ int   g_perm_m[EMAX];
__device__ int   g_cnt_b[ND_MAX + 1];
__device__ int   g_off_b[ND_MAX + 1];
__device__ int   g_cur_b[ND_MAX];
__device__ int   g_perm_b[EMAX];
__device__ float g_ews[EMAX];     // sigmoid(edge_weight)
__device__ int   g_part_m[32];    // per-block partial sums (n <= 65536)
__device__ int   g_part_b[32];
__device__ int   g_done;          // last-block flag for fused reduce+scan

// ---------------------------------------------------------------------------
// tf32 helpers
// ---------------------------------------------------------------------------
__device__ __forceinline__ uint32_t f2tf32(float x) {
    uint32_t r;
    asm("cvt.rna.tf32.f32 %0, %1;" : "=r"(r) : "f"(x));
    return r;
}
__device__ __forceinline__ void mma8(float* cc, const uint32_t* a, const uint32_t* b) {
    asm volatile(
        "mma.sync.aligned.m16n8k8.row.col.f32.tf32.tf32.f32 "
        "{%0,%1,%2,%3}, {%4,%5,%6,%7}, {%8,%9}, {%0,%1,%2,%3};"
        : "+f"(cc[0]), "+f"(cc[1]), "+f"(cc[2]), "+f"(cc[3])
        : "r"(a[0]), "r"(a[1]), "r"(a[2]), "r"(a[3]), "r"(b[0]), "r"(b[1]));
}

// ---------------------------------------------------------------------------
// CSR build
// ---------------------------------------------------------------------------
__global__ __launch_bounds__(256)
void zero_counts_kernel(int n_m, int n_d) {
    int i = blockIdx.x * 256 + threadIdx.x;
    if (i <= n_m) g_cnt_m[i] = 0;
    if (i <= n_d) g_cnt_b[i] = 0;
    if (i == 0)   g_done = 0;
}

__global__ __launch_bounds__(256)
void hist_kernel(const int* __restrict__ dst_m, const int* __restrict__ dst_b,
                 const float* __restrict__ ew, int E) {
    int e = blockIdx.x * 256 + threadIdx.x;
    if (e >= E) return;
    atomicAdd(&g_cnt_m[__ldg(dst_m + e)], 1);
    atomicAdd(&g_cnt_b[__ldg(dst_b + e)], 1);
    g_ews[e] = 1.f / (1.f + __expf(-__ldg(ew + e)));
}

__device__ __forceinline__ void reduce_body(const int* __restrict__ cnt,
                                            int* __restrict__ part, int n, int blk) {
    __shared__ int sw[8];
    int t = threadIdx.x;
    int base = blk * SCAN_CHUNK + t * 8;
    int s = 0;
#pragma unroll
    for (int j = 0; j < 8; ++j) {
        int i = base + j;
        if (i < n) s += __ldg(cnt + i);
    }
    for (int o = 16; o > 0; o >>= 1) s += __shfl_down_sync(0xffffffffu, s, o);
    if ((t & 31) == 0) sw[t >> 5] = s;
    __syncthreads();
    if (t < 8) {
        int v = sw[t];
        for (int o = 4; o > 0; o >>= 1) v += __shfl_down_sync(0xffu, v, o);
        if (t == 0) part[blk] = v;
    }
}

// Fused phase 1+2: per-block partial sums, then LAST block scans the partials.
__global__ __launch_bounds__(256)
void csr_reduce_scan(int n_m, int n_d, int nb_m, int nb_b) {
    if ((int)blockIdx.x < nb_m) reduce_body(g_cnt_m, g_part_m, n_m, blockIdx.x);
    else                        reduce_body(g_cnt_b, g_part_b, n_d, blockIdx.x - nb_m);
    __syncthreads();
    __threadfence();
    __shared__ int isLast;
    if (threadIdx.x == 0) {
        int d = atomicAdd(&g_done, 1);
        isLast = (d == (int)gridDim.x - 1);
    }
    __syncthreads();
    if (isLast) {
        if (threadIdx.x == 0) g_done = 0;
        __threadfence();
        if (threadIdx.x < 64) {
            int w = threadIdx.x >> 5, lane = threadIdx.x & 31;
            int* part = w ? g_part_b : g_part_m;
            int  nb   = w ? nb_b : nb_m;
            int v = (lane < nb) ? part[lane] : 0;
            int x = v;
            for (int o = 1; o < 32; o <<= 1) {
                int y = __shfl_up_sync(0xffffffffu, x, o);
                if (lane >= o) x += y;
            }
            if (lane < nb) part[lane] = x - v;   // exclusive base per block
        }
    }
}

// Phase 3: per-block exclusive scan, write offs[] and cur[]
__device__ __forceinline__ void offs_body(const int* __restrict__ cnt,
                                          const int* __restrict__ part,
                                          int* __restrict__ offs, int* __restrict__ cur,
                                          int n, int blk) {
    __shared__ int sw[8];
    int t = threadIdx.x, lane = t & 31, wid = t >> 5;
    int base = blk * SCAN_CHUNK + t * 8;
    int c[8]; int s = 0;
#pragma unroll
    for (int j = 0; j < 8; ++j) {
        int i = base + j;
        c[j] = (i < n) ? __ldg(cnt + i) : 0;
        s += c[j];
    }
    int x = s;
    for (int o = 1; o < 32; o <<= 1) {
        int y = __shfl_up_sync(0xffffffffu, x, o);
        if (lane >= o) x += y;
    }
    if (lane == 31) sw[wid] = x;
    __syncthreads();
    if (wid == 0) {
        int v = (lane < 8) ? sw[lane] : 0;
        for (int o = 1; o < 8; o <<= 1) {
            int y = __shfl_up_sync(0xffffffffu, v, o);
            if (lane >= o) v += y;
        }
        if (lane < 8) sw[lane] = v;
    }
    __syncthreads();
    int run = part[blk] + (wid ? sw[wid - 1] : 0) + x - s;
#pragma unroll
    for (int j = 0; j < 8; ++j) {
        int i = base + j;
        if (i < n) {
            offs[i] = run;
            cur[i]  = run;
            run += c[j];
            if (i == n - 1) offs[n] = run;
        }
    }
}
__global__ __launch_bounds__(256)
void csr_offsets(int n_m, int n_d, int nb_m) {
    if ((int)blockIdx.x < nb_m)
        offs_body(g_cnt_m, g_part_m, g_off_m, g_cur_m, n_m, blockIdx.x);
    else
        offs_body(g_cnt_b, g_part_b, g_off_b, g_cur_b, n_d, blockIdx.x - nb_m);
}

__global__ __launch_bounds__(256)
void fill_kernel(const int* __restrict__ dst_m, const int* __restrict__ dst_b, int E) {
    int e = blockIdx.x * 256 + threadIdx.x;
    if (e >= E) return;
    int p = atomicAdd(&g_cur_m[__ldg(dst_m + e)], 1);
    g_perm_m[p] = e;
    int q = atomicAdd(&g_cur_b[__ldg(dst_b + e)], 1);
    g_perm_b[q] = e;
}

// ---------------------------------------------------------------------------
// FUSED gather + tensor-core GraphConv:
//   out[m,:] = relu( (sum_{e: dst=m} w_e * x_src[src_e,:]) @ W1
//                    + x_root[m,:] @ W2 + bias )
// Phase 1: 8 warps gather BM=64 dst rows (8 rows/warp) into resident smem.
// Phase 2: tf32 mma k-loop; pass 0 A = resident gather tile, pass 1 A = root
// rows via cp.async; B always cp.async double-buffered. 3-term tf32 split.
// Dynamic smem: 64*132 (agg) + 2*64*20 (root) + 2*16*132 (B) floats = ~59.5KB.
// ---------------------------------------------------------------------------
#define AGP 132   // agg row pitch (132%32=4 -> bank = 4g+c, conflict-free)
#define BKP 20    // root chunk pitch
#define BNP 132   // B row pitch
#define FUSED_SMEM_BYTES ((64 * AGP + 2 * 64 * BKP + 2 * 16 * BNP) * 4)

template <bool WEIGHTED>
__global__ __launch_bounds__(256)
void fused_gather_gemm(const float* __restrict__ x_src,
                       const int*   __restrict__ src,
                       const int*   __restrict__ perm,
                       const int*   __restrict__ offs,
                       const float* __restrict__ x_root,
                       const float* __restrict__ W1,
                       const float* __restrict__ W2,
                       const float* __restrict__ bias,
                       float* __restrict__ out, int M) {
    constexpr int BM = 64, BN = 128, BK = 16, K = 128;
    constexpr int TPP = K / BK;      // 8 chunks per operand pass
    constexpr int NT  = 2 * TPP;     // two passes: agg, root

    extern __shared__ float smem[];
    float* sAgg  = smem;                          // [64][AGP]
    float* sRoot = smem + 64 * AGP;               // [2][64][BKP]
    float* sB    = smem + 64 * AGP + 2 * 64 * BKP;// [2][16][BNP]

    const int t    = threadIdx.x;
    const int lane = t & 31, w = t >> 5;
    const int wm = (w / 4) * 32, wn = (w % 4) * 32;   // warp tile 32x32, WR=2 WC=4
    const int g = lane >> 2, c = lane & 3;
    const int rowBase = blockIdx.x * BM;

    // ---------------- Phase 1: gather 8 rows per warp into sAgg ----------------
#pragma unroll 1
    for (int rr = 0; rr < 8; ++rr) {
        const int r = w * 8 + rr;
        const int d = rowBase + r;
        float4 acc = make_float4(0.f, 0.f, 0.f, 0.f);
        if (d < M) {
            const int start = __ldg(offs + d);
            const int end   = __ldg(offs + d + 1);
            for (int base = start; base < end; base += 32) {
                int i = base + lane;
                int e = (i < end) ? __ldg(perm + i) : 0;
                int s = (i < end) ? __ldg(src + e) : 0;
                float wt = 1.f;
                if (WEIGHTED) wt = (i < end) ? __ldg(g_ews + e) : 0.f;
                int cnt = min(32, end - base);
#pragma unroll 4
                for (int j = 0; j < cnt; ++j) {
                    int   sj = __shfl_sync(0xffffffffu, s, j);
                    float wj = WEIGHTED ? __shfl_sync(0xffffffffu, wt, j) : 1.f;
                    float4 v = *reinterpret_cast<const float4*>(
                        x_src + (size_t)sj * FEAT + lane * 4);
                    if (WEIGHTED) {
                        acc.x = fmaf(wj, v.x, acc.x);
                        acc.y = fmaf(wj, v.y, acc.y);
                        acc.z = fmaf(wj, v.z, acc.z);
                        acc.w = fmaf(wj, v.w, acc.w);
                    } else {
                        acc.x += v.x; acc.y += v.y; acc.z += v.z; acc.w += v.w;
                    }
                }
            }
        }
        float* row = sAgg + r * AGP + lane * 4;
        row[0] = acc.x; row[1] = acc.y; row[2] = acc.z; row[3] = acc.w;
    }
    __syncthreads();

    // ---------------- Phase 2: tf32 GEMM ----------------
    auto stage = [&](int tt) {
        const int buf = tt & 1;
        const int kt  = (tt % TPP) * BK;
        const float* W = (tt >= TPP) ? W2 : W1;
        // B tile: 16 x 128 floats = 512 quads, 2 per thread
#pragma unroll
        for (int q = t; q < BK * (BN / 4); q += 256) {
            int kr = q / (BN / 4);
            int nc = (q % (BN / 4)) * 4;
            const float* srcp = W + (size_t)(kt + kr) * BN + nc;
            uint32_t dst = (uint32_t)__cvta_generic_to_shared(
                &sB[buf * 16 * BNP + kr * BNP + nc]);
            asm volatile("cp.async.ca.shared.global [%0], [%1], 16;"
                         :: "r"(dst), "l"(srcp));
        }
        if (tt >= TPP) {
            // root A chunk: 64 x 16 floats = 256 quads, 1 per thread
            int r  = t >> 2;
            int kk = (t & 3) * 4;
            const float* srcp = x_root + (size_t)(rowBase + r) * K + kt + kk;
            uint32_t dst = (uint32_t)__cvta_generic_to_shared(
                &sRoot[buf * 64 * BKP + r * BKP + kk]);
            int sz = (rowBase + r < M) ? 16 : 0;
            asm volatile("cp.async.ca.shared.global [%0], [%1], 16, %2;"
                         :: "r"(dst), "l"(srcp), "r"(sz));
        }
        asm volatile("cp.async.commit_group;");
    };

    float acc[2][4][4] = {};   // [mi][ni][frag]

    stage(0);
#pragma unroll 1
    for (int tt = 0; tt < NT; ++tt) {
        if (tt + 1 < NT) {
            stage(tt + 1);
            asm volatile("cp.async.wait_group 1;");
        } else {
            asm volatile("cp.async.wait_group 0;");
        }
        __syncthreads();
        const int cur = tt & 1;
        const bool rootPass = (tt >= TPP);
        const int kt = (tt % TPP) * BK;
#pragma unroll
        for (int k8 = 0; k8 < BK / 8; ++k8) {
            const int k0 = k8 * 8;
            // B fragments (hi/lo) for the 4 n-tiles
            uint32_t bh[4][2], bl[4][2];
#pragma unroll
            for (int ni = 0; ni < 4; ++ni)
#pragma unroll
                for (int h = 0; h < 2; ++h) {
                    float b = sB[cur * 16 * BNP + (k0 + c + 4 * h) * BNP + wn + ni * 8 + g];
                    uint32_t hb = f2tf32(b);
                    bh[ni][h] = hb;
                    bl[ni][h] = f2tf32(b - __uint_as_float(hb));
                }
#pragma unroll
            for (int mi = 0; mi < 2; ++mi) {
                float a0, a1, a2, a3;
                if (rootPass) {
                    const float* base = sRoot + cur * 64 * BKP;
                    a0 = base[(wm + mi * 16 + g    ) * BKP + k0 + c];
                    a1 = base[(wm + mi * 16 + g + 8) * BKP + k0 + c];
                    a2 = base[(wm + mi * 16 + g    ) * BKP + k0 + c + 4];
                    a3 = base[(wm + mi * 16 + g + 8) * BKP + k0 + c + 4];
                } else {
                    a0 = sAgg[(wm + mi * 16 + g    ) * AGP + kt + k0 + c];
                    a1 = sAgg[(wm + mi * 16 + g + 8) * AGP + kt + k0 + c];
                    a2 = sAgg[(wm + mi * 16 + g    ) * AGP + kt + k0 + c + 4];
                    a3 = sAgg[(wm + mi * 16 + g + 8) * AGP + kt + k0 + c + 4];
                }
                uint32_t ah[4], al[4];
                ah[0] = f2tf32(a0); al[0] = f2tf32(a0 - __uint_as_float(ah[0]));
                ah[1] = f2tf32(a1); al[1] = f2tf32(a1 - __uint_as_float(ah[1]));
                ah[2] = f2tf32(a2); al[2] = f2tf32(a2 - __uint_as_float(ah[2]));
                ah[3] = f2tf32(a3); al[3] = f2tf32(a3 - __uint_as_float(ah[3]));
#pragma unroll
                for (int ni = 0; ni < 4; ++ni) {
                    mma8(acc[mi][ni], ah, bh[ni]);
                    mma8(acc[mi][ni], ah, bl[ni]);
                    mma8(acc[mi][ni], al, bh[ni]);
                }
            }
        }
        __syncthreads();
    }

    // --- epilogue: bias + ReLU + store ---
#pragma unroll
    for (int mi = 0; mi < 2; ++mi) {
        int r0 = rowBase + wm + mi * 16 + g;
#pragma unroll
        for (int ni = 0; ni < 4; ++ni) {
            int col = wn + ni * 8 + 2 * c;
            float b0 = __ldg(bias + col), b1 = __ldg(bias + col + 1);
            float o0 = fmaxf(acc[mi][ni][0] + b0, 0.f);
            float o1 = fmaxf(acc[mi][ni][1] + b1, 0.f);
            float o2 = fmaxf(acc[mi][ni][2] + b0, 0.f);
            float o3 = fmaxf(acc[mi][ni][3] + b1, 0.f);
            if (r0 < M)
                *reinterpret_cast<float2*>(out + (size_t)r0 * BN + col) = make_float2(o0, o1);
            if (r0 + 8 < M)
                *reinterpret_cast<float2*>(out + (size_t)(r0 + 8) * BN + col) = make_float2(o2, o3);
        }
    }
}

// ---------------------------------------------------------------------------
// Plain tf32 GEMM (final projection, N=64): as in the 280us build.
// ---------------------------------------------------------------------------
template <int BM, int BN, bool HAS2, bool RELU>
__global__ __launch_bounds__(256)
void gemm_tf32(const float* __restrict__ A1, const float* __restrict__ W1,
               const float* __restrict__ A2, const float* __restrict__ W2,
               const float* __restrict__ bias,
               float* __restrict__ out, int M) {
    constexpr int BK = 16, K = 128;
    constexpr int TPP = K / BK;
    constexpr int NT  = HAS2 ? 2 * TPP : TPP;
    constexpr int WC  = BN / 32, WR = BM / 32;
    static_assert(WR * WC == 8, "8 warps");
    constexpr int BKP2 = BK + 4;
    constexpr int BNP2 = BN + 4;

    __shared__ float sA[2][BM][BKP2];
    __shared__ float sBt[2][BK][BNP2];

    const int t    = threadIdx.x;
    const int lane = t & 31, w = t >> 5;
    const int wm = (w / WC) * 32, wn = (w % WC) * 32;
    const int g = lane >> 2, c = lane & 3;
    const int rowBase = blockIdx.x * BM;

    auto stage = [&](int tt) {
        const float* A = (HAS2 && tt >= TPP) ? A2 : A1;
        const float* W = (HAS2 && tt >= TPP) ? W2 : W1;
        const int kt  = (tt % TPP) * BK;
        const int buf = tt & 1;
#pragma unroll
        for (int q = t; q < BM * (BK / 4); q += 256) {
            int r  = q >> 2;
            int kk = (q & 3) * 4;
            const float* srcp = A + (size_t)(rowBase + r) * K + kt + kk;
            uint32_t dst = (uint32_t)__cvta_generic_to_shared(&sA[buf][r][kk]);
            int sz = (rowBase + r < M) ? 16 : 0;
            asm volatile("cp.async.ca.shared.global [%0], [%1], 16, %2;"
                         :: "r"(dst), "l"(srcp), "r"(sz));
        }
#pragma unroll
        for (int q = t; q < BK * (BN / 4); q += 256) {
            int kr = q / (BN / 4);
            int nc = (q % (BN / 4)) * 4;
            const float* srcp = W + (size_t)(kt + kr) * BN + nc;
            uint32_t dst = (uint32_t)__cvta_generic_to_shared(&sBt[buf][kr][nc]);
            asm volatile("cp.async.ca.shared.global [%0], [%1], 16;"
                         :: "r"(dst), "l"(srcp));
        }
        asm volatile("cp.async.commit_group;");
    };

    float acc[2][4][4] = {};

    stage(0);
#pragma unroll 1
    for (int tt = 0; tt < NT; ++tt) {
        if (tt + 1 < NT) {
            stage(tt + 1);
            asm volatile("cp.async.wait_group 1;");
        } else {
            asm volatile("cp.async.wait_group 0;");
        }
        __syncthreads();
        const int cur = tt & 1;
#pragma unroll
        for (int k8 = 0; k8 < BK / 8; ++k8) {
            const int k0 = k8 * 8;
            uint32_t bh[4][2], bl[4][2];
#pragma unroll
            for (int ni = 0; ni < 4; ++ni)
#pragma unroll
                for (int h = 0; h < 2; ++h) {
                    float b = sBt[cur][k0 + c + 4 * h][wn + ni * 8 + g];
                    uint32_t hb = f2tf32(b);
                    bh[ni][h] = hb;
                    bl[ni][h] = f2tf32(b - __uint_as_float(hb));
                }
#pragma unroll
            for (int mi = 0; mi < 2; ++mi) {
                float a0 = sA[cur][wm + mi * 16 + g    ][k0 + c];
                float a1 = sA[cur][wm + mi * 16 + g + 8][k0 + c];
                float a2 = sA[cur][wm + mi * 16 + g    ][k0 + c + 4];
                float a3 = sA[cur][wm + mi * 16 + g + 8][k0 + c + 4];
                uint32_t ah[4], al[4];
                ah[0] = f2tf32(a0); al[0] = f2tf32(a0 - __uint_as_float(ah[0]));
                ah[1] = f2tf32(a1); al[1] = f2tf32(a1 - __uint_as_float(ah[1]));
                ah[2] = f2tf32(a2); al[2] = f2tf32(a2 - __uint_as_float(ah[2]));
                ah[3] = f2tf32(a3); al[3] = f2tf32(a3 - __uint_as_float(ah[3]));
#pragma unroll
                for (int ni = 0; ni < 4; ++ni) {
                    mma8(acc[mi][ni], ah, bh[ni]);
                    mma8(acc[mi][ni], ah, bl[ni]);
                    mma8(acc[mi][ni], al, bh[ni]);
                }
            }
        }
        __syncthreads();
    }

#pragma unroll
    for (int mi = 0; mi < 2; ++mi) {
        int r0 = rowBase + wm + mi * 16 + g;
#pragma unroll
        for (int ni = 0; ni < 4; ++ni) {
            int col = wn + ni * 8 + 2 * c;
            float b0 = __ldg(bias + col), b1 = __ldg(bias + col + 1);
            float o0 = acc[mi][ni][0] + b0, o1 = acc[mi][ni][1] + b1;
            float o2 = acc[mi][ni][2] + b0, o3 = acc[mi][ni][3] + b1;
            if (RELU) {
                o0 = fmaxf(o0, 0.f); o1 = fmaxf(o1, 0.f);
                o2 = fmaxf(o2, 0.f); o3 = fmaxf(o3, 0.f);
            }
            if (r0 < M)
                *reinterpret_cast<float2*>(out + (size_t)r0 * BN + col) = make_float2(o0, o1);
            if (r0 + 8 < M)
                *reinterpret_cast<float2*>(out + (size_t)(r0 + 8) * BN + col) = make_float2(o2, o3);
        }
    }
}

// ---------------------------------------------------------------------------
// Launch
// ---------------------------------------------------------------------------
extern "C" void kernel_launch(void* const* d_in, const int* in_sizes, int n_in,
                              void* d_out, int out_size) {
    const float* x_meas  = (const float*)d_in[0];
    const float* x_dem   = (const float*)d_in[1];
    const int*   src_m   = (const int*)  d_in[2];
    const int*   dst_m   = (const int*)  d_in[3];
    const int*   src_b   = (const int*)  d_in[4];
    const int*   dst_b   = (const int*)  d_in[5];
    const float* eweight = (const float*)d_in[6];
    const float* W_rel1  = (const float*)d_in[7];
    const float* b_rel1  = (const float*)d_in[8];
    const float* W_root1 = (const float*)d_in[9];
    const float* W_rel2  = (const float*)d_in[10];
    const float* b_rel2  = (const float*)d_in[11];
    const float* W_root2 = (const float*)d_in[12];
    const float* W_rel3  = (const float*)d_in[13];
    const float* b_rel3  = (const float*)d_in[14];
    const float* W_root3 = (const float*)d_in[15];
    const float* W_lin   = (const float*)d_in[16];
    const float* b_lin   = (const float*)d_in[17];
    float* out = (float*)d_out;

    const int n_m = in_sizes[0] / FEAT;
    const int n_d = in_sizes[1] / FEAT;
    const int E   = in_sizes[2];

    float *movie, *user1, *user2;
    cudaGetSymbolAddress((void**)&movie, g_movie);
    cudaGetSymbolAddress((void**)&user1, g_user1);
    cudaGetSymbolAddress((void**)&user2, g_user2);
    int *off_m, *off_b, *perm_m, *perm_b;
    cudaGetSymbolAddress((void**)&off_m,  g_off_m);
    cudaGetSymbolAddress((void**)&off_b,  g_off_b);
    cudaGetSymbolAddress((void**)&perm_m, g_perm_m);
    cudaGetSymbolAddress((void**)&perm_b, g_perm_b);

    // Raise dynamic-smem limit for the fused kernels (~59.5KB). Host attribute
    // call: capture-safe, idempotent.
    static bool attrs_set = false;
    if (!attrs_set) {
        cudaFuncSetAttribute(fused_gather_gemm<false>,
                             cudaFuncAttributeMaxDynamicSharedMemorySize, FUSED_SMEM_BYTES);
        cudaFuncSetAttribute(fused_gather_gemm<true>,
                             cudaFuncAttributeMaxDynamicSharedMemorySize, FUSED_SMEM_BYTES);
        attrs_set = true;
    }

    const int eb   = (E + 255) / 256;
    const int nb_m = (n_m + SCAN_CHUNK - 1) / SCAN_CHUNK;   // <= 32
    const int nb_b = (n_d + SCAN_CHUNK - 1) / SCAN_CHUNK;   // <= 32

    // --- CSR build: zero, hist, fused reduce+scan, offsets, fill ---
    zero_counts_kernel<<<(n_m + 256) / 256, 256>>>(n_m, n_d);
    hist_kernel<<<eb, 256>>>(dst_m, dst_b, eweight, E);
    csr_reduce_scan<<<nb_m + nb_b, 256>>>(n_m, n_d, nb_m, nb_b);
    csr_offsets<<<nb_m + nb_b, 256>>>(n_m, n_d, nb_m);
    fill_kernel<<<eb, 256>>>(dst_m, dst_b, E);

    // --- Layer 1: fused gather+GEMM (movie graph, unweighted) ---
    fused_gather_gemm<false><<<(n_m + 63) / 64, 256, FUSED_SMEM_BYTES>>>(
        x_meas, src_m, perm_m, off_m, x_meas, W_rel1, W_root1, b_rel1, movie, n_m);

    // --- Layer 2: fused gather+GEMM (bipartite, weighted) ---
    fused_gather_gemm<true><<<(n_d + 63) / 64, 256, FUSED_SMEM_BYTES>>>(
        x_meas, src_b, perm_b, off_b, x_dem, W_rel2, W_root2, b_rel2, user1, n_d);

    // --- Layer 3: fused gather+GEMM (bipartite, weighted, from movie) ---
    fused_gather_gemm<true><<<(n_d + 63) / 64, 256, FUSED_SMEM_BYTES>>>(
        movie, src_b, perm_b, off_b, user1, W_rel3, W_root3, b_rel3, user2, n_d);

    // --- Output projection (N=64) ---
    gemm_tf32<128, 64, false, false><<<(n_d + 127) / 128, 256>>>(
        user2, W_lin, nullptr, nullptr, b_lin, out, n_d);
}

// round 16
// speedup vs baseline: 1.2408x; 1.2408x over previous
#include <cuda_runtime.h>
#include <math.h>
#include <string.h>
#include <stdint.h>

// ---------------------------------------------------------------------------
// Problem constants
// ---------------------------------------------------------------------------
#define NM_MAX 50000
#define ND_MAX 20000
#define EMAX   700000
#define FEAT   128
#define KP     64        // K/2 pairs per row
#define SCAN_CHUNK 2048

// ---------------------------------------------------------------------------
// Scratch (device globals: allocation-free rule)
// ---------------------------------------------------------------------------
__device__ float    g_movie[(size_t)NM_MAX * FEAT];        // fp32 (gather src)
// bf16 hi/lo packed-pair arrays: [M][KP] u32, elem = {lo:bf16(x[2p]), hi:bf16(x[2p+1])}
__device__ uint32_t g_xmh[(size_t)NM_MAX * KP], g_xml[(size_t)NM_MAX * KP];
__device__ uint32_t g_xdh[(size_t)ND_MAX * KP], g_xdl[(size_t)ND_MAX * KP];
__device__ uint32_t g_aAh[(size_t)NM_MAX * KP], g_aAl[(size_t)NM_MAX * KP];
__device__ uint32_t g_aBh[(size_t)ND_MAX * KP], g_aBl[(size_t)ND_MAX * KP];
__device__ uint32_t g_u1h[(size_t)ND_MAX * KP], g_u1l[(size_t)ND_MAX * KP];
__device__ uint32_t g_u2h[(size_t)ND_MAX * KP], g_u2l[(size_t)ND_MAX * KP];
// weight splits: [K/2][N] pair arrays, 6x(64*128) + 64*64 = 53248 u32
#define WOFF_REL1 0
#define WOFF_ROOT1 8192
#define WOFF_REL2 16384
#define WOFF_ROOT2 24576
#define WOFF_REL3 32768
#define WOFF_ROOT3 40960
#define WOFF_LIN  49152
#define WTOTAL    53248
__device__ uint32_t g_wh[WTOTAL], g_wl[WTOTAL];

// CSR-build scratch
__device__ int   g_cnt_m[NM_MAX + 1];
__device__ int   g_off_m[NM_MAX + 1];
__device__ int   g_cur_m[NM_MAX];
__device__ int   g_perm_m[EMAX];
__device__ int   g_cnt_b[ND_MAX + 1];
__device__ int   g_off_b[ND_MAX + 1];
__device__ int   g_cur_b[ND_MAX];
__device__ int   g_perm_b[EMAX];
__device__ float g_ews[EMAX];
__device__ int   g_part_m[32];
__device__ int   g_part_b[32];
__device__ int   g_done;

// ---------------------------------------------------------------------------
// bf16 split helpers
// ---------------------------------------------------------------------------
// Returns packed {lo:bf16(e0), hi:bf16(e1)}; writes residual pack to lo_pack.
__device__ __forceinline__ uint32_t packsplit(float e0, float e1, uint32_t& lo_pack) {
    uint32_t h;
    asm("cvt.rn.bf16x2.f32 %0, %1, %2;" : "=r"(h) : "f"(e1), "f"(e0));
    float f0 = __uint_as_float(h << 16);
    float f1 = __uint_as_float(h & 0xffff0000u);
    asm("cvt.rn.bf16x2.f32 %0, %1, %2;" : "=r"(lo_pack) : "f"(e1 - f1), "f"(e0 - f0));
    return h;
}

__device__ __forceinline__ void mma16(float* cc, const uint32_t* a, const uint32_t* b) {
    asm volatile(
        "mma.sync.aligned.m16n8k16.row.col.f32.bf16.bf16.f32 "
        "{%0,%1,%2,%3}, {%4,%5,%6,%7}, {%8,%9}, {%0,%1,%2,%3};"
        : "+f"(cc[0]), "+f"(cc[1]), "+f"(cc[2]), "+f"(cc[3])
        : "r"(a[0]), "r"(a[1]), "r"(a[2]), "r"(a[3]), "r"(b[0]), "r"(b[1]));
}

#define CPASYNC16(dst, src) \
    asm volatile("cp.async.ca.shared.global [%0], [%1], 16;" \
                 :: "r"(dst), "l"(src))
#define CPASYNC16Z(dst, src, sz) \
    asm volatile("cp.async.ca.shared.global [%0], [%1], 16, %2;" \
                 :: "r"(dst), "l"(src), "r"(sz))

// ---------------------------------------------------------------------------
// CSR build (unchanged from 280us build)
// ---------------------------------------------------------------------------
__global__ __launch_bounds__(256)
void zero_counts_kernel(int n_m, int n_d) {
    int i = blockIdx.x * 256 + threadIdx.x;
    if (i <= n_m) g_cnt_m[i] = 0;
    if (i <= n_d) g_cnt_b[i] = 0;
    if (i == 0)   g_done = 0;
}

__global__ __launch_bounds__(256)
void hist_kernel(const int* __restrict__ dst_m, const int* __restrict__ dst_b,
                 const float* __restrict__ ew, int E) {
    int e = blockIdx.x * 256 + threadIdx.x;
    if (e >= E) return;
    atomicAdd(&g_cnt_m[__ldg(dst_m + e)], 1);
    atomicAdd(&g_cnt_b[__ldg(dst_b + e)], 1);
    g_ews[e] = 1.f / (1.f + __expf(-__ldg(ew + e)));
}

__device__ __forceinline__ void reduce_body(const int* __restrict__ cnt,
                                            int* __restrict__ part, int n, int blk) {
    __shared__ int sw[8];
    int t = threadIdx.x;
    int base = blk * SCAN_CHUNK + t * 8;
    int s = 0;
#pragma unroll
    for (int j = 0; j < 8; ++j) {
        int i = base + j;
        if (i < n) s += __ldg(cnt + i);
    }
    for (int o = 16; o > 0; o >>= 1) s += __shfl_down_sync(0xffffffffu, s, o);
    if ((t & 31) == 0) sw[t >> 5] = s;
    __syncthreads();
    if (t < 8) {
        int v = sw[t];
        for (int o = 4; o > 0; o >>= 1) v += __shfl_down_sync(0xffu, v, o);
        if (t == 0) part[blk] = v;
    }
}

__global__ __launch_bounds__(256)
void csr_reduce_scan(int n_m, int n_d, int nb_m, int nb_b) {
    if ((int)blockIdx.x < nb_m) reduce_body(g_cnt_m, g_part_m, n_m, blockIdx.x);
    else                        reduce_body(g_cnt_b, g_part_b, n_d, blockIdx.x - nb_m);
    __syncthreads();
    __threadfence();
    __shared__ int isLast;
    if (threadIdx.x == 0) {
        int d = atomicAdd(&g_done, 1);
        isLast = (d == (int)gridDim.x - 1);
    }
    __syncthreads();
    if (isLast) {
        if (threadIdx.x == 0) g_done = 0;
        __threadfence();
        if (threadIdx.x < 64) {
            int w = threadIdx.x >> 5, lane = threadIdx.x & 31;
            int* part = w ? g_part_b : g_part_m;
            int  nb   = w ? nb_b : nb_m;
            int v = (lane < nb) ? part[lane] : 0;
            int x = v;
            for (int o = 1; o < 32; o <<= 1) {
                int y = __shfl_up_sync(0xffffffffu, x, o);
                if (lane >= o) x += y;
            }
            if (lane < nb) part[lane] = x - v;
        }
    }
}

__device__ __forceinline__ void offs_body(const int* __restrict__ cnt,
                                          const int* __restrict__ part,
                                          int* __restrict__ offs, int* __restrict__ cur,
                                          int n, int blk) {
    __shared__ int sw[8];
    int t = threadIdx.x, lane = t & 31, wid = t >> 5;
    int base = blk * SCAN_CHUNK + t * 8;
    int c[8]; int s = 0;
#pragma unroll
    for (int j = 0; j < 8; ++j) {
        int i = base + j;
        c[j] = (i < n) ? __ldg(cnt + i) : 0;
        s += c[j];
    }
    int x = s;
    for (int o = 1; o < 32; o <<= 1) {
        int y = __shfl_up_sync(0xffffffffu, x, o);
        if (lane >= o) x += y;
    }
    if (lane == 31) sw[wid] = x;
    __syncthreads();
    if (wid == 0) {
        int v = (lane < 8) ? sw[lane] : 0;
        for (int o = 1; o < 8; o <<= 1) {
            int y = __shfl_up_sync(0xffffffffu, v, o);
            if (lane >= o) v += y;
        }
        if (lane < 8) sw[lane] = v;
    }
    __syncthreads();
    int run = part[blk] + (wid ? sw[wid - 1] : 0) + x - s;
#pragma unroll
    for (int j = 0; j < 8; ++j) {
        int i = base + j;
        if (i < n) {
            offs[i] = run;
            cur[i]  = run;
            run += c[j];
            if (i == n - 1) offs[n] = run;
        }
    }
}
__global__ __launch_bounds__(256)
void csr_offsets(int n_m, int n_d, int nb_m) {
    if ((int)blockIdx.x < nb_m)
        offs_body(g_cnt_m, g_part_m, g_off_m, g_cur_m, n_m, blockIdx.x);
    else
        offs_body(g_cnt_b, g_part_b, g_off_b, g_cur_b, n_d, blockIdx.x - nb_m);
}

__global__ __launch_bounds__(256)
void fill_kernel(const int* __restrict__ dst_m, const int* __restrict__ dst_b, int E) {
    int e = blockIdx.x * 256 + threadIdx.x;
    if (e >= E) return;
    int p = atomicAdd(&g_cur_m[__ldg(dst_m + e)], 1);
    g_perm_m[p] = e;
    int q = atomicAdd(&g_cur_b[__ldg(dst_b + e)], 1);
    g_perm_b[q] = e;
}

// ---------------------------------------------------------------------------
// Pre-split kernels
// ---------------------------------------------------------------------------
// Rows along K (adjacent pairs in memory): X[M*K] fp32 -> Xh/Xl [M*KP] u32
__global__ __launch_bounds__(256)
void split_rows(const float* __restrict__ X, uint32_t* __restrict__ Xh,
                uint32_t* __restrict__ Xl, int npairs) {
    int i = blockIdx.x * 256 + threadIdx.x;
    if (i >= npairs) return;
    float2 v = reinterpret_cast<const float2*>(X)[i];
    uint32_t l, h = packsplit(v.x, v.y, l);
    Xh[i] = h; Xl[i] = l;
}

// Weights W[K][N] row-major -> pair arrays [K/2][N] (pairs along K).
__global__ __launch_bounds__(256)
void split_weights(const float* w0, const float* w1, const float* w2,
                   const float* w3, const float* w4, const float* w5,
                   const float* w6) {
    int i = blockIdx.x * 256 + threadIdx.x;
    if (i >= WTOTAL) return;
    const float* W; int p, n, N;
    if (i < WOFF_LIN) {
        int wsel = i / 8192, j = i % 8192;
        p = j / 128; n = j % 128; N = 128;
        const float* ws[6] = {w0, w1, w2, w3, w4, w5};
        W = ws[wsel];
    } else {
        int j = i - WOFF_LIN;
        p = j / 64; n = j % 64; N = 64;
        W = w6;
    }
    float e0 = __ldg(W + (2 * p) * N + n);
    float e1 = __ldg(W + (2 * p + 1) * N + n);
    uint32_t l, h = packsplit(e0, e1, l);
    g_wh[i] = h; g_wl[i] = l;
}

// ---------------------------------------------------------------------------
// Gather aggregation: one warp per dst node; epilogue writes bf16-split pairs.
// ---------------------------------------------------------------------------
template <bool WEIGHTED>
__global__ __launch_bounds__(256)
void agg_gather(const float* __restrict__ x,
                const int*   __restrict__ src,
                const int*   __restrict__ perm,
                const int*   __restrict__ offs,
                uint32_t*    __restrict__ aggh,
                uint32_t*    __restrict__ aggl,
                int n_dst) {
    int d = blockIdx.x * 8 + (threadIdx.x >> 5);
    if (d >= n_dst) return;
    const int lane  = threadIdx.x & 31;
    const int start = __ldg(offs + d);
    const int end   = __ldg(offs + d + 1);

    float4 acc = make_float4(0.f, 0.f, 0.f, 0.f);
    for (int base = start; base < end; base += 32) {
        int i = base + lane;
        int e = (i < end) ? __ldg(perm + i) : 0;
        int s = (i < end) ? __ldg(src + e) : 0;
        float w = 1.f;
        if (WEIGHTED) w = (i < end) ? __ldg(g_ews + e) : 0.f;
        int cnt = min(32, end - base);
#pragma unroll 4
        for (int j = 0; j < cnt; ++j) {
            int   sj = __shfl_sync(0xffffffffu, s, j);
            float wj = WEIGHTED ? __shfl_sync(0xffffffffu, w, j) : 1.f;
            float4 v = *reinterpret_cast<const float4*>(x + (size_t)sj * FEAT + lane * 4);
            if (WEIGHTED) {
                acc.x = fmaf(wj, v.x, acc.x);
                acc.y = fmaf(wj, v.y, acc.y);
                acc.z = fmaf(wj, v.z, acc.z);
                acc.w = fmaf(wj, v.w, acc.w);
            } else {
                acc.x += v.x; acc.y += v.y; acc.z += v.z; acc.w += v.w;
            }
        }
    }
    uint32_t l0, h0 = packsplit(acc.x, acc.y, l0);
    uint32_t l1, h1 = packsplit(acc.z, acc.w, l1);
    reinterpret_cast<uint2*>(aggh + (size_t)d * KP)[lane] = make_uint2(h0, h1);
    reinterpret_cast<uint2*>(aggl + (size_t)d * KP)[lane] = make_uint2(l0, l1);
}

// ---------------------------------------------------------------------------
// bf16 tensor-core fused GraphConv GEMM (pre-split operands, no in-loop cvt):
//   out = act( A1@W1 + (HAS2 ? A2@W2 : 0) + bias )
// A*, W* are packed bf16 pair arrays (hi & lo). 2-term split:
//   D += ah*bh + ah*bl + al*bh   (error ~2^-18 per product)
// 256 thr / 8 warps; warp tile 32x32; mma m16n8k16; BK=16 (8 pairs)/tile,
// double-buffered cp.async. OUTMODE: 0 = fp32 out, 1 = split (hi/lo) out.
// ---------------------------------------------------------------------------
template <int BM, int BN, bool HAS2, bool RELU, int OUTMODE>
__global__ __launch_bounds__(256)
void gemm_bf16(const uint32_t* __restrict__ A1h, const uint32_t* __restrict__ A1l,
               const uint32_t* __restrict__ W1h, const uint32_t* __restrict__ W1l,
               const uint32_t* __restrict__ A2h, const uint32_t* __restrict__ A2l,
               const uint32_t* __restrict__ W2h, const uint32_t* __restrict__ W2l,
               const float* __restrict__ bias,
               float* __restrict__ outF,
               uint32_t* __restrict__ outH, uint32_t* __restrict__ outL,
               int M) {
    constexpr int TPP = 8;                    // 8 pair-chunks (BK=16) per pass
    constexpr int NT  = HAS2 ? 2 * TPP : TPP;
    constexpr int AP  = 12;                   // A row pitch (u32): 48B, 16B-aligned, conflict-free
    constexpr int BP  = BN + 4;               // B row pitch (u32): 16B-aligned
    constexpr int WC  = BN / 32;

    __shared__ uint32_t sAh[2][BM * AP], sAl[2][BM * AP];
    __shared__ uint32_t sBh[2][8 * BP],  sBl[2][8 * BP];

    const int t    = threadIdx.x;
    const int lane = t & 31, w = t >> 5;
    const int wm = (w / WC) * 32, wn = (w % WC) * 32;
    const int g = lane >> 2, c = lane & 3;
    const int rowBase = blockIdx.x * BM;

    auto stage = [&](int tt) {
        const int buf = tt & 1;
        const int kp  = (tt % TPP) * 8;
        const uint32_t* Ah = (HAS2 && tt >= TPP) ? A2h : A1h;
        const uint32_t* Al = (HAS2 && tt >= TPP) ? A2l : A1l;
        const uint32_t* Bh = (HAS2 && tt >= TPP) ? W2h : W1h;
        const uint32_t* Bl = (HAS2 && tt >= TPP) ? W2l : W1l;
        // A: BM rows x 8 u32, 2 16B-chunks/row, both halves
#pragma unroll
        for (int q = t; q < BM * 2; q += 256) {
            int r = q >> 1, off = (q & 1) * 4;
            size_t gidx = (size_t)(rowBase + r) * KP + kp + off;
            int sz = (rowBase + r < M) ? 16 : 0;
            uint32_t d1 = (uint32_t)__cvta_generic_to_shared(&sAh[buf][r * AP + off]);
            uint32_t d2 = (uint32_t)__cvta_generic_to_shared(&sAl[buf][r * AP + off]);
            CPASYNC16Z(d1, Ah + gidx, sz);
            CPASYNC16Z(d2, Al + gidx, sz);
        }
        // B: 8 pair-rows x BN u32, both halves
#pragma unroll
        for (int q = t; q < 8 * (BN / 4); q += 256) {
            int kr = q / (BN / 4), nc = (q % (BN / 4)) * 4;
            size_t gidx = (size_t)(kp + kr) * BN + nc;
            uint32_t d1 = (uint32_t)__cvta_generic_to_shared(&sBh[buf][kr * BP + nc]);
            uint32_t d2 = (uint32_t)__cvta_generic_to_shared(&sBl[buf][kr * BP + nc]);
            CPASYNC16(d1, Bh + gidx);
            CPASYNC16(d2, Bl + gidx);
        }
        asm volatile("cp.async.commit_group;");
    };

    float acc[2][4][4] = {};   // [mi][ni][frag]

    stage(0);
#pragma unroll 1
    for (int tt = 0; tt < NT; ++tt) {
        if (tt + 1 < NT) {
            stage(tt + 1);
            asm volatile("cp.async.wait_group 1;");
        } else {
            asm volatile("cp.async.wait_group 0;");
        }
        __syncthreads();
        const int buf = tt & 1;

        // A fragments: a0:(g,2c..2c+1) a1:(g+8,..) a2:(g,2c+8..) a3:(g+8,..)
        uint32_t ah[2][4], al[2][4];
#pragma unroll
        for (int mi = 0; mi < 2; ++mi) {
            int r0 = (wm + mi * 16 + g) * AP;
            int r1 = r0 + 8 * AP;
            ah[mi][0] = sAh[buf][r0 + c];     ah[mi][1] = sAh[buf][r1 + c];
            ah[mi][2] = sAh[buf][r0 + c + 4]; ah[mi][3] = sAh[buf][r1 + c + 4];
            al[mi][0] = sAl[buf][r0 + c];     al[mi][1] = sAl[buf][r1 + c];
            al[mi][2] = sAl[buf][r0 + c + 4]; al[mi][3] = sAl[buf][r1 + c + 4];
        }
        // B fragments: b0:(2c..2c+1, col) b1:(2c+8..2c+9, col)
        uint32_t bh[4][2], bl[4][2];
#pragma unroll
        for (int ni = 0; ni < 4; ++ni) {
            int col = wn + ni * 8 + g;
            bh[ni][0] = sBh[buf][c * BP + col];
            bh[ni][1] = sBh[buf][(c + 4) * BP + col];
            bl[ni][0] = sBl[buf][c * BP + col];
            bl[ni][1] = sBl[buf][(c + 4) * BP + col];
        }
#pragma unroll
        for (int mi = 0; mi < 2; ++mi)
#pragma unroll
            for (int ni = 0; ni < 4; ++ni) {
                mma16(acc[mi][ni], ah[mi], bh[ni]);
                mma16(acc[mi][ni], ah[mi], bl[ni]);
                mma16(acc[mi][ni], al[mi], bh[ni]);
            }
        __syncthreads();
    }

    // --- epilogue ---
#pragma unroll
    for (int mi = 0; mi < 2; ++mi) {
        int r0 = rowBase + wm + mi * 16 + g;
#pragma unroll
        for (int ni = 0; ni < 4; ++ni) {
            int col = wn + ni * 8 + 2 * c;
            float b0 = __ldg(bias + col), b1 = __ldg(bias + col + 1);
            float o0 = acc[mi][ni][0] + b0, o1 = acc[mi][ni][1] + b1;
            float o2 = acc[mi][ni][2] + b0, o3 = acc[mi][ni][3] + b1;
            if (RELU) {
                o0 = fmaxf(o0, 0.f); o1 = fmaxf(o1, 0.f);
                o2 = fmaxf(o2, 0.f); o3 = fmaxf(o3, 0.f);
            }
            if (OUTMODE == 0) {
                if (r0 < M)
                    *reinterpret_cast<float2*>(outF + (size_t)r0 * BN + col) = make_float2(o0, o1);
                if (r0 + 8 < M)
                    *reinterpret_cast<float2*>(outF + (size_t)(r0 + 8) * BN + col) = make_float2(o2, o3);
            } else {
                int pcol = (wn >> 1) + ni * 4 + c;
                if (r0 < M) {
                    uint32_t l, h = packsplit(o0, o1, l);
                    outH[(size_t)r0 * (BN / 2) + pcol] = h;
                    outL[(size_t)r0 * (BN / 2) + pcol] = l;
                }
                if (r0 + 8 < M) {
                    uint32_t l, h = packsplit(o2, o3, l);
                    outH[(size_t)(r0 + 8) * (BN / 2) + pcol] = h;
                    outL[(size_t)(r0 + 8) * (BN / 2) + pcol] = l;
                }
            }
        }
    }
}

// ---------------------------------------------------------------------------
// Launch
// ---------------------------------------------------------------------------
extern "C" void kernel_launch(void* const* d_in, const int* in_sizes, int n_in,
                              void* d_out, int out_size) {
    const float* x_meas  = (const float*)d_in[0];
    const float* x_dem   = (const float*)d_in[1];
    const int*   src_m   = (const int*)  d_in[2];
    const int*   dst_m   = (const int*)  d_in[3];
    const int*   src_b   = (const int*)  d_in[4];
    const int*   dst_b   = (const int*)  d_in[5];
    const float* eweight = (const float*)d_in[6];
    const float* W_rel1  = (const float*)d_in[7];
    const float* b_rel1  = (const float*)d_in[8];
    const float* W_root1 = (const float*)d_in[9];
    const float* W_rel2  = (const float*)d_in[10];
    const float* b_rel2  = (const float*)d_in[11];
    const float* W_root2 = (const float*)d_in[12];
    const float* W_rel3  = (const float*)d_in[13];
    const float* b_rel3  = (const float*)d_in[14];
    const float* W_root3 = (const float*)d_in[15];
    const float* W_lin   = (const float*)d_in[16];
    const float* b_lin   = (const float*)d_in[17];
    float* out = (float*)d_out;

    const int n_m = in_sizes[0] / FEAT;
    const int n_d = in_sizes[1] / FEAT;
    const int E   = in_sizes[2];

    float* movie;
    cudaGetSymbolAddress((void**)&movie, g_movie);
    uint32_t *xmh, *xml, *xdh, *xdl, *aAh, *aAl, *aBh, *aBl;
    uint32_t *u1h, *u1l, *u2h, *u2l, *wh, *wl;
    cudaGetSymbolAddress((void**)&xmh, g_xmh);  cudaGetSymbolAddress((void**)&xml, g_xml);
    cudaGetSymbolAddress((void**)&xdh, g_xdh);  cudaGetSymbolAddress((void**)&xdl, g_xdl);
    cudaGetSymbolAddress((void**)&aAh, g_aAh);  cudaGetSymbolAddress((void**)&aAl, g_aAl);
    cudaGetSymbolAddress((void**)&aBh, g_aBh);  cudaGetSymbolAddress((void**)&aBl, g_aBl);
    cudaGetSymbolAddress((void**)&u1h, g_u1h);  cudaGetSymbolAddress((void**)&u1l, g_u1l);
    cudaGetSymbolAddress((void**)&u2h, g_u2h);  cudaGetSymbolAddress((void**)&u2l, g_u2l);
    cudaGetSymbolAddress((void**)&wh,  g_wh);   cudaGetSymbolAddress((void**)&wl,  g_wl);
    int *off_m, *off_b, *perm_m, *perm_b;
    cudaGetSymbolAddress((void**)&off_m,  g_off_m);
    cudaGetSymbolAddress((void**)&off_b,  g_off_b);
    cudaGetSymbolAddress((void**)&perm_m, g_perm_m);
    cudaGetSymbolAddress((void**)&perm_b, g_perm_b);

    const int eb   = (E + 255) / 256;
    const int nb_m = (n_m + SCAN_CHUNK - 1) / SCAN_CHUNK;
    const int nb_b = (n_d + SCAN_CHUNK - 1) / SCAN_CHUNK;

    // --- CSR build ---
    zero_counts_kernel<<<(n_m + 256) / 256, 256>>>(n_m, n_d);
    hist_kernel<<<eb, 256>>>(dst_m, dst_b, eweight, E);
    csr_reduce_scan<<<nb_m + nb_b, 256>>>(n_m, n_d, nb_m, nb_b);
    csr_offsets<<<nb_m + nb_b, 256>>>(n_m, n_d, nb_m);
    fill_kernel<<<eb, 256>>>(dst_m, dst_b, E);

    // --- pre-split roots + weights ---
    split_rows<<<(n_m * KP + 255) / 256, 256>>>(x_meas, xmh, xml, n_m * KP);
    split_rows<<<(n_d * KP + 255) / 256, 256>>>(x_dem,  xdh, xdl, n_d * KP);
    split_weights<<<(WTOTAL + 255) / 256, 256>>>(
        W_rel1, W_root1, W_rel2, W_root2, W_rel3, W_root3, W_lin);

    // --- Layer 1+2 gathers (split output) ---
    agg_gather<false><<<(n_m + 7) / 8, 256>>>(x_meas, src_m, perm_m, off_m, aAh, aAl, n_m);
    agg_gather<true ><<<(n_d + 7) / 8, 256>>>(x_meas, src_b, perm_b, off_b, aBh, aBl, n_d);

    // --- Layer 1 GEMM -> movie (fp32, gather src for L3) ---
    gemm_bf16<64, 128, true, true, 0><<<(n_m + 63) / 64, 256>>>(
        aAh, aAl, wh + WOFF_REL1, wl + WOFF_REL1,
        xmh, xml, wh + WOFF_ROOT1, wl + WOFF_ROOT1,
        b_rel1, movie, nullptr, nullptr, n_m);

    // --- Layer 2 GEMM -> user1 (split, root for L3) ---
    gemm_bf16<64, 128, true, true, 1><<<(n_d + 63) / 64, 256>>>(
        aBh, aBl, wh + WOFF_REL2, wl + WOFF_REL2,
        xdh, xdl, wh + WOFF_ROOT2, wl + WOFF_ROOT2,
        b_rel2, nullptr, u1h, u1l, n_d);

    // --- Layer 3 gather (from movie) + GEMM -> user2 (split) ---
    agg_gather<true><<<(n_d + 7) / 8, 256>>>(movie, src_b, perm_b, off_b, aBh, aBl, n_d);
    gemm_bf16<64, 128, true, true, 1><<<(n_d + 63) / 64, 256>>>(
        aBh, aBl, wh + WOFF_REL3, wl + WOFF_REL3,
        u1h, u1l, wh + WOFF_ROOT3, wl + WOFF_ROOT3,
        b_rel3, nullptr, u2h, u2l, n_d);

    // --- Output projection (N=64, fp32 out) ---
    gemm_bf16<128, 64, false, false, 0><<<(n_d + 127) / 128, 256>>>(
        u2h, u2l, wh + WOFF_LIN, wl + WOFF_LIN,
        nullptr, nullptr, nullptr, nullptr,
        b_lin, out, nullptr, nullptr, n_d);
}

// round 17
// speedup vs baseline: 1.2924x; 1.0415x over previous
#include <cuda_runtime.h>
#include <math.h>
#include <string.h>
#include <stdint.h>

// ---------------------------------------------------------------------------
// Problem constants
// ---------------------------------------------------------------------------
#define NM_MAX 50000
#define ND_MAX 20000
#define EMAX   700000
#define FEAT   128
#define KP     64        // K/2 pairs per row
#define SCAN_CHUNK 2048

// ---------------------------------------------------------------------------
// Scratch (device globals: allocation-free rule)
// ---------------------------------------------------------------------------
__device__ float    g_movie[(size_t)NM_MAX * FEAT];        // fp32 (gather src)
// bf16 hi/lo packed-pair arrays: [M][KP] u32, elem = {lo:bf16(x[2p]), hi:bf16(x[2p+1])}
__device__ uint32_t g_xmh[(size_t)NM_MAX * KP], g_xml[(size_t)NM_MAX * KP];
__device__ uint32_t g_xdh[(size_t)ND_MAX * KP], g_xdl[(size_t)ND_MAX * KP];
__device__ uint32_t g_aAh[(size_t)NM_MAX * KP], g_aAl[(size_t)NM_MAX * KP];
__device__ uint32_t g_aBh[(size_t)ND_MAX * KP], g_aBl[(size_t)ND_MAX * KP];
__device__ uint32_t g_u1h[(size_t)ND_MAX * KP], g_u1l[(size_t)ND_MAX * KP];
__device__ uint32_t g_u2h[(size_t)ND_MAX * KP], g_u2l[(size_t)ND_MAX * KP];
// weight splits: [K/2][N] pair arrays
#define WOFF_REL1 0
#define WOFF_ROOT1 8192
#define WOFF_REL2 16384
#define WOFF_ROOT2 24576
#define WOFF_REL3 32768
#define WOFF_ROOT3 40960
#define WOFF_LIN  49152
#define WTOTAL    53248
__device__ uint32_t g_wh[WTOTAL], g_wl[WTOTAL];

// CSR-build scratch. Sorted edge payloads (dst-major order):
//   movie graph: src id only. bipartite: {src id, sigmoid(ew) bits} as uint2.
__device__ int   g_cnt_m[NM_MAX + 1];
__device__ int   g_off_m[NM_MAX + 1];
__device__ int   g_cur_m[NM_MAX];
__device__ int   g_esrc_m[EMAX];
__device__ int   g_cnt_b[ND_MAX + 1];
__device__ int   g_off_b[ND_MAX + 1];
__device__ int   g_cur_b[ND_MAX];
__device__ uint2 g_eb[EMAX];
__device__ int   g_part_m[32];
__device__ int   g_part_b[32];
__device__ int   g_done;

// ---------------------------------------------------------------------------
// bf16 split helpers
// ---------------------------------------------------------------------------
// Returns packed {lo:bf16(e0), hi:bf16(e1)}; writes residual pack to lo_pack.
__device__ __forceinline__ uint32_t packsplit(float e0, float e1, uint32_t& lo_pack) {
    uint32_t h;
    asm("cvt.rn.bf16x2.f32 %0, %1, %2;" : "=r"(h) : "f"(e1), "f"(e0));
    float f0 = __uint_as_float(h << 16);
    float f1 = __uint_as_float(h & 0xffff0000u);
    asm("cvt.rn.bf16x2.f32 %0, %1, %2;" : "=r"(lo_pack) : "f"(e1 - f1), "f"(e0 - f0));
    return h;
}

__device__ __forceinline__ void mma16(float* cc, const uint32_t* a, const uint32_t* b) {
    asm volatile(
        "mma.sync.aligned.m16n8k16.row.col.f32.bf16.bf16.f32 "
        "{%0,%1,%2,%3}, {%4,%5,%6,%7}, {%8,%9}, {%0,%1,%2,%3};"
        : "+f"(cc[0]), "+f"(cc[1]), "+f"(cc[2]), "+f"(cc[3])
        : "r"(a[0]), "r"(a[1]), "r"(a[2]), "r"(a[3]), "r"(b[0]), "r"(b[1]));
}

#define CPASYNC16(dst, src) \
    asm volatile("cp.async.ca.shared.global [%0], [%1], 16;" \
                 :: "r"(dst), "l"(src))
#define CPASYNC16Z(dst, src, sz) \
    asm volatile("cp.async.ca.shared.global [%0], [%1], 16, %2;" \
                 :: "r"(dst), "l"(src), "r"(sz))

// ---------------------------------------------------------------------------
// CSR build
// ---------------------------------------------------------------------------
__global__ __launch_bounds__(256)
void zero_counts_kernel(int n_m, int n_d) {
    int i = blockIdx.x * 256 + threadIdx.x;
    if (i <= n_m) g_cnt_m[i] = 0;
    if (i <= n_d) g_cnt_b[i] = 0;
    if (i == 0)   g_done = 0;
}

__global__ __launch_bounds__(256)
void hist_kernel(const int* __restrict__ dst_m, const int* __restrict__ dst_b, int E) {
    int e = blockIdx.x * 256 + threadIdx.x;
    if (e >= E) return;
    atomicAdd(&g_cnt_m[__ldg(dst_m + e)], 1);
    atomicAdd(&g_cnt_b[__ldg(dst_b + e)], 1);
}

__device__ __forceinline__ void reduce_body(const int* __restrict__ cnt,
                                            int* __restrict__ part, int n, int blk) {
    __shared__ int sw[8];
    int t = threadIdx.x;
    int base = blk * SCAN_CHUNK + t * 8;
    int s = 0;
#pragma unroll
    for (int j = 0; j < 8; ++j) {
        int i = base + j;
        if (i < n) s += __ldg(cnt + i);
    }
    for (int o = 16; o > 0; o >>= 1) s += __shfl_down_sync(0xffffffffu, s, o);
    if ((t & 31) == 0) sw[t >> 5] = s;
    __syncthreads();
    if (t < 8) {
        int v = sw[t];
        for (int o = 4; o > 0; o >>= 1) v += __shfl_down_sync(0xffu, v, o);
        if (t == 0) part[blk] = v;
    }
}

__global__ __launch_bounds__(256)
void csr_reduce_scan(int n_m, int n_d, int nb_m, int nb_b) {
    if ((int)blockIdx.x < nb_m) reduce_body(g_cnt_m, g_part_m, n_m, blockIdx.x);
    else                        reduce_body(g_cnt_b, g_part_b, n_d, blockIdx.x - nb_m);
    __syncthreads();
    __threadfence();
    __shared__ int isLast;
    if (threadIdx.x == 0) {
        int d = atomicAdd(&g_done, 1);
        isLast = (d == (int)gridDim.x - 1);
    }
    __syncthreads();
    if (isLast) {
        if (threadIdx.x == 0) g_done = 0;
        __threadfence();
        if (threadIdx.x < 64) {
            int w = threadIdx.x >> 5, lane = threadIdx.x & 31;
            int* part = w ? g_part_b : g_part_m;
            int  nb   = w ? nb_b : nb_m;
            int v = (lane < nb) ? part[lane] : 0;
            int x = v;
            for (int o = 1; o < 32; o <<= 1) {
                int y = __shfl_up_sync(0xffffffffu, x, o);
                if (lane >= o) x += y;
            }
            if (lane < nb) part[lane] = x - v;
        }
    }
}

__device__ __forceinline__ void offs_body(const int* __restrict__ cnt,
                                          const int* __restrict__ part,
                                          int* __restrict__ offs, int* __restrict__ cur,
                                          int n, int blk) {
    __shared__ int sw[8];
    int t = threadIdx.x, lane = t & 31, wid = t >> 5;
    int base = blk * SCAN_CHUNK + t * 8;
    int c[8]; int s = 0;
#pragma unroll
    for (int j = 0; j < 8; ++j) {
        int i = base + j;
        c[j] = (i < n) ? __ldg(cnt + i) : 0;
        s += c[j];
    }
    int x = s;
    for (int o = 1; o < 32; o <<= 1) {
        int y = __shfl_up_sync(0xffffffffu, x, o);
        if (lane >= o) x += y;
    }
    if (lane == 31) sw[wid] = x;
    __syncthreads();
    if (wid == 0) {
        int v = (lane < 8) ? sw[lane] : 0;
        for (int o = 1; o < 8; o <<= 1) {
            int y = __shfl_up_sync(0xffffffffu, v, o);
            if (lane >= o) v += y;
        }
        if (lane < 8) sw[lane] = v;
    }
    __syncthreads();
    int run = part[blk] + (wid ? sw[wid - 1] : 0) + x - s;
#pragma unroll
    for (int j = 0; j < 8; ++j) {
        int i = base + j;
        if (i < n) {
            offs[i] = run;
            cur[i]  = run;
            run += c[j];
            if (i == n - 1) offs[n] = run;
        }
    }
}
__global__ __launch_bounds__(256)
void csr_offsets(int n_m, int n_d, int nb_m) {
    if ((int)blockIdx.x < nb_m)
        offs_body(g_cnt_m, g_part_m, g_off_m, g_cur_m, n_m, blockIdx.x);
    else
        offs_body(g_cnt_b, g_part_b, g_off_b, g_cur_b, n_d, blockIdx.x - nb_m);
}

// Fill: write sorted edge PAYLOADS (src id; src+sigmoid(ew) for bipartite).
// Gathers then read edge meta fully coalesced, no perm indirection.
__global__ __launch_bounds__(256)
void fill_kernel(const int* __restrict__ dst_m, const int* __restrict__ src_m,
                 const int* __restrict__ dst_b, const int* __restrict__ src_b,
                 const float* __restrict__ ew, int E) {
    int e = blockIdx.x * 256 + threadIdx.x;
    if (e >= E) return;
    int p = atomicAdd(&g_cur_m[__ldg(dst_m + e)], 1);
    g_esrc_m[p] = __ldg(src_m + e);
    int q = atomicAdd(&g_cur_b[__ldg(dst_b + e)], 1);
    float w = 1.f / (1.f + __expf(-__ldg(ew + e)));
    g_eb[q] = make_uint2((uint32_t)__ldg(src_b + e), __float_as_uint(w));
}

// ---------------------------------------------------------------------------
// Pre-split kernels
// ---------------------------------------------------------------------------
__global__ __launch_bounds__(256)
void split_rows(const float* __restrict__ X, uint32_t* __restrict__ Xh,
                uint32_t* __restrict__ Xl, int npairs) {
    int i = blockIdx.x * 256 + threadIdx.x;
    if (i >= npairs) return;
    float2 v = reinterpret_cast<const float2*>(X)[i];
    uint32_t l, h = packsplit(v.x, v.y, l);
    Xh[i] = h; Xl[i] = l;
}

__global__ __launch_bounds__(256)
void split_weights(const float* w0, const float* w1, const float* w2,
                   const float* w3, const float* w4, const float* w5,
                   const float* w6) {
    int i = blockIdx.x * 256 + threadIdx.x;
    if (i >= WTOTAL) return;
    const float* W; int p, n, N;
    if (i < WOFF_LIN) {
        int wsel = i / 8192, j = i % 8192;
        p = j / 128; n = j % 128; N = 128;
        const float* ws[6] = {w0, w1, w2, w3, w4, w5};
        W = ws[wsel];
    } else {
        int j = i - WOFF_LIN;
        p = j / 64; n = j % 64; N = 64;
        W = w6;
    }
    float e0 = __ldg(W + (2 * p) * N + n);
    float e1 = __ldg(W + (2 * p + 1) * N + n);
    uint32_t l, h = packsplit(e0, e1, l);
    g_wh[i] = h; g_wl[i] = l;
}

// ---------------------------------------------------------------------------
// Gather aggregation: one warp per dst node; coalesced sorted edge payloads;
// epilogue writes bf16-split pairs.
// ---------------------------------------------------------------------------
template <bool WEIGHTED>
__global__ __launch_bounds__(256)
void agg_gather(const float* __restrict__ x,
                const int*   __restrict__ esrc,   // sorted src ids (unweighted)
                const uint2* __restrict__ epay,   // sorted {src, ew} (weighted)
                const int*   __restrict__ offs,
                uint32_t*    __restrict__ aggh,
                uint32_t*    __restrict__ aggl,
                int n_dst) {
    int d = blockIdx.x * 8 + (threadIdx.x >> 5);
    if (d >= n_dst) return;
    const int lane  = threadIdx.x & 31;
    const int start = __ldg(offs + d);
    const int end   = __ldg(offs + d + 1);

    float4 acc = make_float4(0.f, 0.f, 0.f, 0.f);
    for (int base = start; base < end; base += 32) {
        int i = base + lane;
        int s = 0; float w = 0.f;
        if (i < end) {
            if (WEIGHTED) {
                uint2 pv = __ldg(epay + i);
                s = (int)pv.x; w = __uint_as_float(pv.y);
            } else {
                s = __ldg(esrc + i);
            }
        }
        int cnt = min(32, end - base);
#pragma unroll 4
        for (int j = 0; j < cnt; ++j) {
            int   sj = __shfl_sync(0xffffffffu, s, j);
            float wj = WEIGHTED ? __shfl_sync(0xffffffffu, w, j) : 1.f;
            float4 v = *reinterpret_cast<const float4*>(x + (size_t)sj * FEAT + lane * 4);
            if (WEIGHTED) {
                acc.x = fmaf(wj, v.x, acc.x);
                acc.y = fmaf(wj, v.y, acc.y);
                acc.z = fmaf(wj, v.z, acc.z);
                acc.w = fmaf(wj, v.w, acc.w);
            } else {
                acc.x += v.x; acc.y += v.y; acc.z += v.z; acc.w += v.w;
            }
        }
    }
    uint32_t l0, h0 = packsplit(acc.x, acc.y, l0);
    uint32_t l1, h1 = packsplit(acc.z, acc.w, l1);
    reinterpret_cast<uint2*>(aggh + (size_t)d * KP)[lane] = make_uint2(h0, h1);
    reinterpret_cast<uint2*>(aggl + (size_t)d * KP)[lane] = make_uint2(l0, l1);
}

// ---------------------------------------------------------------------------
// bf16 tensor-core fused GraphConv GEMM (pre-split operands, no in-loop cvt).
// 2-term split: D += ah*bh + ah*bl + al*bh.
// OUTMODE: 0 = fp32 out, 1 = split (hi/lo) out.
// ---------------------------------------------------------------------------
template <int BM, int BN, bool HAS2, bool RELU, int OUTMODE>
__global__ __launch_bounds__(256)
void gemm_bf16(const uint32_t* __restrict__ A1h, const uint32_t* __restrict__ A1l,
               const uint32_t* __restrict__ W1h, const uint32_t* __restrict__ W1l,
               const uint32_t* __restrict__ A2h, const uint32_t* __restrict__ A2l,
               const uint32_t* __restrict__ W2h, const uint32_t* __restrict__ W2l,
               const float* __restrict__ bias,
               float* __restrict__ outF,
               uint32_t* __restrict__ outH, uint32_t* __restrict__ outL,
               int M) {
    constexpr int TPP = 8;
    constexpr int NT  = HAS2 ? 2 * TPP : TPP;
    constexpr int AP  = 12;
    constexpr int BP  = BN + 4;
    constexpr int WC  = BN / 32;

    __shared__ uint32_t sAh[2][BM * AP], sAl[2][BM * AP];
    __shared__ uint32_t sBh[2][8 * BP],  sBl[2][8 * BP];

    const int t    = threadIdx.x;
    const int lane = t & 31, w = t >> 5;
    const int wm = (w / WC) * 32, wn = (w % WC) * 32;
    const int g = lane >> 2, c = lane & 3;
    const int rowBase = blockIdx.x * BM;

    auto stage = [&](int tt) {
        const int buf = tt & 1;
        const int kp  = (tt % TPP) * 8;
        const uint32_t* Ah = (HAS2 && tt >= TPP) ? A2h : A1h;
        const uint32_t* Al = (HAS2 && tt >= TPP) ? A2l : A1l;
        const uint32_t* Bh = (HAS2 && tt >= TPP) ? W2h : W1h;
        const uint32_t* Bl = (HAS2 && tt >= TPP) ? W2l : W1l;
#pragma unroll
        for (int q = t; q < BM * 2; q += 256) {
            int r = q >> 1, off = (q & 1) * 4;
            size_t gidx = (size_t)(rowBase + r) * KP + kp + off;
            int sz = (rowBase + r < M) ? 16 : 0;
            uint32_t d1 = (uint32_t)__cvta_generic_to_shared(&sAh[buf][r * AP + off]);
            uint32_t d2 = (uint32_t)__cvta_generic_to_shared(&sAl[buf][r * AP + off]);
            CPASYNC16Z(d1, Ah + gidx, sz);
            CPASYNC16Z(d2, Al + gidx, sz);
        }
#pragma unroll
        for (int q = t; q < 8 * (BN / 4); q += 256) {
            int kr = q / (BN / 4), nc = (q % (BN / 4)) * 4;
            size_t gidx = (size_t)(kp + kr) * BN + nc;
            uint32_t d1 = (uint32_t)__cvta_generic_to_shared(&sBh[buf][kr * BP + nc]);
            uint32_t d2 = (uint32_t)__cvta_generic_to_shared(&sBl[buf][kr * BP + nc]);
            CPASYNC16(d1, Bh + gidx);
            CPASYNC16(d2, Bl + gidx);
        }
        asm volatile("cp.async.commit_group;");
    };

    float acc[2][4][4] = {};

    stage(0);
#pragma unroll 1
    for (int tt = 0; tt < NT; ++tt) {
        if (tt + 1 < NT) {
            stage(tt + 1);
            asm volatile("cp.async.wait_group 1;");
        } else {
            asm volatile("cp.async.wait_group 0;");
        }
        __syncthreads();
        const int buf = tt & 1;

        uint32_t ah[2][4], al[2][4];
#pragma unroll
        for (int mi = 0; mi < 2; ++mi) {
            int r0 = (wm + mi * 16 + g) * AP;
            int r1 = r0 + 8 * AP;
            ah[mi][0] = sAh[buf][r0 + c];     ah[mi][1] = sAh[buf][r1 + c];
            ah[mi][2] = sAh[buf][r0 + c + 4]; ah[mi][3] = sAh[buf][r1 + c + 4];
            al[mi][0] = sAl[buf][r0 + c];     al[mi][1] = sAl[buf][r1 + c];
            al[mi][2] = sAl[buf][r0 + c + 4]; al[mi][3] = sAl[buf][r1 + c + 4];
        }
        uint32_t bh[4][2], bl[4][2];
#pragma unroll
        for (int ni = 0; ni < 4; ++ni) {
            int col = wn + ni * 8 + g;
            bh[ni][0] = sBh[buf][c * BP + col];
            bh[ni][1] = sBh[buf][(c + 4) * BP + col];
            bl[ni][0] = sBl[buf][c * BP + col];
            bl[ni][1] = sBl[buf][(c + 4) * BP + col];
        }
#pragma unroll
        for (int mi = 0; mi < 2; ++mi)
#pragma unroll
            for (int ni = 0; ni < 4; ++ni) {
                mma16(acc[mi][ni], ah[mi], bh[ni]);
                mma16(acc[mi][ni], ah[mi], bl[ni]);
                mma16(acc[mi][ni], al[mi], bh[ni]);
            }
        __syncthreads();
    }

#pragma unroll
    for (int mi = 0; mi < 2; ++mi) {
        int r0 = rowBase + wm + mi * 16 + g;
#pragma unroll
        for (int ni = 0; ni < 4; ++ni) {
            int col = wn + ni * 8 + 2 * c;
            float b0 = __ldg(bias + col), b1 = __ldg(bias + col + 1);
            float o0 = acc[mi][ni][0] + b0, o1 = acc[mi][ni][1] + b1;
            float o2 = acc[mi][ni][2] + b0, o3 = acc[mi][ni][3] + b1;
            if (RELU) {
                o0 = fmaxf(o0, 0.f); o1 = fmaxf(o1, 0.f);
                o2 = fmaxf(o2, 0.f); o3 = fmaxf(o3, 0.f);
            }
            if (OUTMODE == 0) {
                if (r0 < M)
                    *reinterpret_cast<float2*>(outF + (size_t)r0 * BN + col) = make_float2(o0, o1);
                if (r0 + 8 < M)
                    *reinterpret_cast<float2*>(outF + (size_t)(r0 + 8) * BN + col) = make_float2(o2, o3);
            } else {
                int pcol = (wn >> 1) + ni * 4 + c;
                if (r0 < M) {
                    uint32_t l, h = packsplit(o0, o1, l);
                    outH[(size_t)r0 * (BN / 2) + pcol] = h;
                    outL[(size_t)r0 * (BN / 2) + pcol] = l;
                }
                if (r0 + 8 < M) {
                    uint32_t l, h = packsplit(o2, o3, l);
                    outH[(size_t)(r0 + 8) * (BN / 2) + pcol] = h;
                    outL[(size_t)(r0 + 8) * (BN / 2) + pcol] = l;
                }
            }
        }
    }
}

// ---------------------------------------------------------------------------
// Launch
// ---------------------------------------------------------------------------
extern "C" void kernel_launch(void* const* d_in, const int* in_sizes, int n_in,
                              void* d_out, int out_size) {
    const float* x_meas  = (const float*)d_in[0];
    const float* x_dem   = (const float*)d_in[1];
    const int*   src_m   = (const int*)  d_in[2];
    const int*   dst_m   = (const int*)  d_in[3];
    const int*   src_b   = (const int*)  d_in[4];
    const int*   dst_b   = (const int*)  d_in[5];
    const float* eweight = (const float*)d_in[6];
    const float* W_rel1  = (const float*)d_in[7];
    const float* b_rel1  = (const float*)d_in[8];
    const float* W_root1 = (const float*)d_in[9];
    const float* W_rel2  = (const float*)d_in[10];
    const float* b_rel2  = (const float*)d_in[11];
    const float* W_root2 = (const float*)d_in[12];
    const float* W_rel3  = (const float*)d_in[13];
    const float* b_rel3  = (const float*)d_in[14];
    const float* W_root3 = (const float*)d_in[15];
    const float* W_lin   = (const float*)d_in[16];
    const float* b_lin   = (const float*)d_in[17];
    float* out = (float*)d_out;

    const int n_m = in_sizes[0] / FEAT;
    const int n_d = in_sizes[1] / FEAT;
    const int E   = in_sizes[2];

    float* movie;
    cudaGetSymbolAddress((void**)&movie, g_movie);
    uint32_t *xmh, *xml, *xdh, *xdl, *aAh, *aAl, *aBh, *aBl;
    uint32_t *u1h, *u1l, *u2h, *u2l, *wh, *wl;
    cudaGetSymbolAddress((void**)&xmh, g_xmh);  cudaGetSymbolAddress((void**)&xml, g_xml);
    cudaGetSymbolAddress((void**)&xdh, g_xdh);  cudaGetSymbolAddress((void**)&xdl, g_xdl);
    cudaGetSymbolAddress((void**)&aAh, g_aAh);  cudaGetSymbolAddress((void**)&aAl, g_aAl);
    cudaGetSymbolAddress((void**)&aBh, g_aBh);  cudaGetSymbolAddress((void**)&aBl, g_aBl);
    cudaGetSymbolAddress((void**)&u1h, g_u1h);  cudaGetSymbolAddress((void**)&u1l, g_u1l);
    cudaGetSymbolAddress((void**)&u2h, g_u2h);  cudaGetSymbolAddress((void**)&u2l, g_u2l);
    cudaGetSymbolAddress((void**)&wh,  g_wh);   cudaGetSymbolAddress((void**)&wl,  g_wl);
    int *off_m, *off_b, *esrc_m;
    uint2* eb;
    cudaGetSymbolAddress((void**)&off_m,  g_off_m);
    cudaGetSymbolAddress((void**)&off_b,  g_off_b);
    cudaGetSymbolAddress((void**)&esrc_m, g_esrc_m);
    cudaGetSymbolAddress((void**)&eb,     g_eb);

    const int ebks = (E + 255) / 256;
    const int nb_m = (n_m + SCAN_CHUNK - 1) / SCAN_CHUNK;
    const int nb_b = (n_d + SCAN_CHUNK - 1) / SCAN_CHUNK;

    // --- CSR build (sorted edge payloads) ---
    zero_counts_kernel<<<(n_m + 256) / 256, 256>>>(n_m, n_d);
    hist_kernel<<<ebks, 256>>>(dst_m, dst_b, E);
    csr_reduce_scan<<<nb_m + nb_b, 256>>>(n_m, n_d, nb_m, nb_b);
    csr_offsets<<<nb_m + nb_b, 256>>>(n_m, n_d, nb_m);
    fill_kernel<<<ebks, 256>>>(dst_m, src_m, dst_b, src_b, eweight, E);

    // --- pre-split roots + weights ---
    split_rows<<<(n_m * KP + 255) / 256, 256>>>(x_meas, xmh, xml, n_m * KP);
    split_rows<<<(n_d * KP + 255) / 256, 256>>>(x_dem,  xdh, xdl, n_d * KP);
    split_weights<<<(WTOTAL + 255) / 256, 256>>>(
        W_rel1, W_root1, W_rel2, W_root2, W_rel3, W_root3, W_lin);

    // --- Layer 1+2 gathers (coalesced meta, split output) ---
    agg_gather<false><<<(n_m + 7) / 8, 256>>>(x_meas, esrc_m, nullptr, off_m, aAh, aAl, n_m);
    agg_gather<true ><<<(n_d + 7) / 8, 256>>>(x_meas, nullptr, eb, off_b, aBh, aBl, n_d);

    // --- Layer 1 GEMM -> movie (fp32, gather src for L3) ---
    gemm_bf16<64, 128, true, true, 0><<<(n_m + 63) / 64, 256>>>(
        aAh, aAl, wh + WOFF_REL1, wl + WOFF_REL1,
        xmh, xml, wh + WOFF_ROOT1, wl + WOFF_ROOT1,
        b_rel1, movie, nullptr, nullptr, n_m);

    // --- Layer 2 GEMM -> user1 (split, root for L3) ---
    gemm_bf16<64, 128, true, true, 1><<<(n_d + 63) / 64, 256>>>(
        aBh, aBl, wh + WOFF_REL2, wl + WOFF_REL2,
        xdh, xdl, wh + WOFF_ROOT2, wl + WOFF_ROOT2,
        b_rel2, nullptr, u1h, u1l, n_d);

    // --- Layer 3 gather (from movie) + GEMM -> user2 (split) ---
    agg_gather<true><<<(n_d + 7) / 8, 256>>>(movie, nullptr, eb, off_b, aBh, aBl, n_d);
    gemm_bf16<64, 128, true, true, 1><<<(n_d + 63) / 64, 256>>>(
        aBh, aBl, wh + WOFF_REL3, wl + WOFF_REL3,
        u1h, u1l, wh + WOFF_ROOT3, wl + WOFF_ROOT3,
        b_rel3, nullptr, u2h, u2l, n_d);

    // --- Output projection (N=64, fp32 out) ---
    gemm_bf16<128, 64, false, false, 0><<<(n_d + 127) / 128, 256>>>(
        u2h, u2l, wh + WOFF_LIN, wl + WOFF_LIN,
        nullptr, nullptr, nullptr, nullptr,
        b_lin, out, nullptr, nullptr, n_d);
}